// round 2
// baseline (speedup 1.0000x reference)
#include <cuda_runtime.h>
#include <math.h>

#define NNODE 8192
#define NEDGE 262144
#define KF    512
#define NH    512
#define NO    64

// ---------------- scratch (static device memory: allowed) ----------------
__device__ float g_buf1[NNODE * NH];   // gemm1 out
__device__ float g_buf2[NNODE * NH];   // agg1 out (relu)  -> gemm2 input
__device__ float g_buf3[NNODE * NH];   // gemm2 out
__device__ float g_xhid[NNODE * NH];   // relu(conv2) = x_hid
__device__ float g_xn  [NNODE * NH];   // row-normalized x_hid
__device__ float g_dinv[NNODE];
__device__ int   g_cnt [NNODE];
__device__ int   g_off [NNODE + 1];
__device__ int   g_cur [NNODE];
__device__ int   g_ssrc[NEDGE];

// ---------------- CSR build ----------------
__global__ void k_zero() {
    int i = blockIdx.x * blockDim.x + threadIdx.x;
    if (i < NNODE) g_cnt[i] = 0;
}

__global__ void k_count(const int* __restrict__ dst) {
    int i = blockIdx.x * blockDim.x + threadIdx.x;
    if (i < NEDGE) atomicAdd(&g_cnt[dst[i]], 1);
}

// 1 block, 1024 threads, 8 elems/thread: exclusive scan + dinv + cursor init
__global__ void k_scan() {
    __shared__ int ssum[1024];
    int t = threadIdx.x;
    int base = t * 8;
    int c[8];
    int s = 0;
#pragma unroll
    for (int i = 0; i < 8; i++) { c[i] = g_cnt[base + i]; s += c[i]; }
    ssum[t] = s;
    __syncthreads();
    for (int off = 1; off < 1024; off <<= 1) {
        int v = (t >= off) ? ssum[t - off] : 0;
        __syncthreads();
        ssum[t] += v;
        __syncthreads();
    }
    int excl = ssum[t] - s;
#pragma unroll
    for (int i = 0; i < 8; i++) {
        g_off[base + i] = excl;
        g_cur[base + i] = excl;
        g_dinv[base + i] = rsqrtf((float)c[i] + 1.0f);  // +1 self loop
        excl += c[i];
    }
    if (t == 1023) g_off[NNODE] = ssum[1023];
}

__global__ void k_fill(const int* __restrict__ src, const int* __restrict__ dst) {
    int i = blockIdx.x * blockDim.x + threadIdx.x;
    if (i < NEDGE) {
        int p = atomicAdd(&g_cur[dst[i]], 1);
        g_ssrc[p] = src[i];
    }
}

// ---------------- SGEMM NN: C[M,N] = A[M,K] @ B[K,N] (row-major) ----------------
// 128x128 tile, BK=8, 256 threads, 8x8 per thread. Dims assumed multiples of tile.
__global__ __launch_bounds__(256) void k_sgemm_nn(
    const float* __restrict__ A, const float* __restrict__ B, float* __restrict__ C,
    int K, int Nc)
{
    __shared__ float As[8][128];
    __shared__ float Bs[8][128];
    int tid = threadIdx.x;
    const float* Ab = A + (size_t)blockIdx.y * 128 * K;
    const float* Bb = B + (size_t)blockIdx.x * 128;

    int arow = tid >> 1, aoff = (tid & 1) * 4;      // A: 128x8
    int brow = tid >> 5, boff = (tid & 31) * 4;     // B: 8x128

    int tr = (tid >> 4) * 8;
    int tc = (tid & 15) * 8;
    float acc[8][8];
#pragma unroll
    for (int i = 0; i < 8; i++)
#pragma unroll
        for (int j = 0; j < 8; j++) acc[i][j] = 0.f;

    for (int k0 = 0; k0 < K; k0 += 8) {
        float4 av = *(const float4*)(Ab + (size_t)arow * K + k0 + aoff);
        As[aoff + 0][arow] = av.x;
        As[aoff + 1][arow] = av.y;
        As[aoff + 2][arow] = av.z;
        As[aoff + 3][arow] = av.w;
        *(float4*)&Bs[brow][boff] = *(const float4*)(Bb + (size_t)(k0 + brow) * Nc + boff);
        __syncthreads();
#pragma unroll
        for (int k = 0; k < 8; k++) {
            float ra[8], rb[8];
            *(float4*)&ra[0] = *(float4*)&As[k][tr];
            *(float4*)&ra[4] = *(float4*)&As[k][tr + 4];
            *(float4*)&rb[0] = *(float4*)&Bs[k][tc];
            *(float4*)&rb[4] = *(float4*)&Bs[k][tc + 4];
#pragma unroll
            for (int i = 0; i < 8; i++)
#pragma unroll
                for (int j = 0; j < 8; j++) acc[i][j] += ra[i] * rb[j];
        }
        __syncthreads();
    }
    int row0 = blockIdx.y * 128 + tr;
    int col0 = blockIdx.x * 128 + tc;
#pragma unroll
    for (int i = 0; i < 8; i++) {
#pragma unroll
        for (int j = 0; j < 8; j += 4) {
            float4 v = make_float4(acc[i][j], acc[i][j+1], acc[i][j+2], acc[i][j+3]);
            *(float4*)&C[(size_t)(row0 + i) * Nc + col0 + j] = v;
        }
    }
}

// ---------------- GCN aggregation: out[d] = dinv[d]*sum(dinv[s]*h[s]) + dinv[d]^2*h[d] + b ----------------
__global__ __launch_bounds__(128) void k_agg(
    const float* __restrict__ h, const float* __restrict__ bias,
    float* __restrict__ out, int do_relu)
{
    int d = blockIdx.x;
    int t = threadIdx.x;
    const float4* h4 = (const float4*)h;
    float4 acc = make_float4(0.f, 0.f, 0.f, 0.f);
    int e = g_off[d], end = g_off[d + 1];
    for (; e < end; ++e) {
        int s = g_ssrc[e];
        float w = g_dinv[s];
        float4 v = h4[(size_t)s * 128 + t];
        acc.x += v.x * w; acc.y += v.y * w; acc.z += v.z * w; acc.w += v.w * w;
    }
    float wd = g_dinv[d];
    float w2 = wd * wd;
    float4 sv = h4[(size_t)d * 128 + t];
    float4 bb = ((const float4*)bias)[t];
    float4 r;
    r.x = acc.x * wd + sv.x * w2 + bb.x;
    r.y = acc.y * wd + sv.y * w2 + bb.y;
    r.z = acc.z * wd + sv.z * w2 + bb.z;
    r.w = acc.w * wd + sv.w * w2 + bb.w;
    if (do_relu) {
        r.x = fmaxf(r.x, 0.f); r.y = fmaxf(r.y, 0.f);
        r.z = fmaxf(r.z, 0.f); r.w = fmaxf(r.w, 0.f);
    }
    ((float4*)out)[(size_t)d * 128 + t] = r;
}

// ---------------- row L2-normalize ----------------
__global__ __launch_bounds__(128) void k_norm(const float* __restrict__ x, float* __restrict__ xn) {
    __shared__ float red[4];
    int r = blockIdx.x, t = threadIdx.x;
    float4 v = ((const float4*)x)[(size_t)r * 128 + t];
    float s = v.x * v.x + v.y * v.y + v.z * v.z + v.w * v.w;
#pragma unroll
    for (int o = 16; o; o >>= 1) s += __shfl_xor_sync(0xffffffffu, s, o);
    if ((t & 31) == 0) red[t >> 5] = s;
    __syncthreads();
    float tot = red[0] + red[1] + red[2] + red[3];
    float inv = (tot > 0.f) ? rsqrtf(tot) : 0.f;
    ((float4*)xn)[(size_t)r * 128 + t] = make_float4(v.x*inv, v.y*inv, v.z*inv, v.w*inv);
}

// ---------------- FC head: logits = x_hid @ fcW + fcb  (8192x64, K=512) ----------------
__global__ __launch_bounds__(256) void k_fc(
    const float* __restrict__ X, const float* __restrict__ W,
    const float* __restrict__ bias, float* __restrict__ out)
{
    __shared__ float Xs[32][68];   // 68-float stride keeps float4 alignment (272B)
    __shared__ float Ws[64][NO];
    int tid = threadIdx.x;
    int tx = tid & 63;    // output col
    int tg = tid >> 6;    // row group 0..3 (8 rows each)
    int row0 = blockIdx.x * 32;
    float acc[8];
#pragma unroll
    for (int i = 0; i < 8; i++) acc[i] = 0.f;

    for (int k0 = 0; k0 < NH; k0 += 64) {
        int xr = tid >> 3, xk = (tid & 7) * 8;
        *(float4*)&Xs[xr][xk]     = *(const float4*)&X[(size_t)(row0 + xr) * NH + k0 + xk];
        *(float4*)&Xs[xr][xk + 4] = *(const float4*)&X[(size_t)(row0 + xr) * NH + k0 + xk + 4];
        int wr = tid >> 2, wc = (tid & 3) * 16;
#pragma unroll
        for (int q = 0; q < 16; q += 4)
            *(float4*)&Ws[wr][wc + q] = *(const float4*)&W[(size_t)(k0 + wr) * NO + wc + q];
        __syncthreads();
#pragma unroll 16
        for (int k = 0; k < 64; k++) {
            float w = Ws[k][tx];
#pragma unroll
            for (int i = 0; i < 8; i++) acc[i] += Xs[tg * 8 + i][k] * w;
        }
        __syncthreads();
    }
#pragma unroll
    for (int i = 0; i < 8; i++)
        out[(size_t)(row0 + tg * 8 + i) * NO + tx] = acc[i] + bias[tx];
}

// ---------------- cosine matrix: C = Xn @ Xn^T, zero diag, symmetric (upper triangle + mirror) ----------------
__global__ __launch_bounds__(256) void k_dis(const float* __restrict__ X, float* __restrict__ C) {
    int bx = blockIdx.x, by = blockIdx.y;
    if (bx < by) return;   // symmetry: only col-block >= row-block

    __shared__ float As[8][128];
    __shared__ float Bs[8][128];
    int tid = threadIdx.x;
    const float* Ab = X + (size_t)by * 128 * KF;
    const float* Bb = X + (size_t)bx * 128 * KF;

    int lrow = tid >> 1, loff = (tid & 1) * 4;   // same pattern both tiles (128x8)
    int tr = (tid >> 4) * 8;
    int tc = (tid & 15) * 8;
    float acc[8][8];
#pragma unroll
    for (int i = 0; i < 8; i++)
#pragma unroll
        for (int j = 0; j < 8; j++) acc[i][j] = 0.f;

    for (int k0 = 0; k0 < KF; k0 += 8) {
        float4 av = *(const float4*)(Ab + (size_t)lrow * KF + k0 + loff);
        As[loff + 0][lrow] = av.x;
        As[loff + 1][lrow] = av.y;
        As[loff + 2][lrow] = av.z;
        As[loff + 3][lrow] = av.w;
        float4 bv = *(const float4*)(Bb + (size_t)lrow * KF + k0 + loff);
        Bs[loff + 0][lrow] = bv.x;
        Bs[loff + 1][lrow] = bv.y;
        Bs[loff + 2][lrow] = bv.z;
        Bs[loff + 3][lrow] = bv.w;
        __syncthreads();
#pragma unroll
        for (int k = 0; k < 8; k++) {
            float ra[8], rb[8];
            *(float4*)&ra[0] = *(float4*)&As[k][tr];
            *(float4*)&ra[4] = *(float4*)&As[k][tr + 4];
            *(float4*)&rb[0] = *(float4*)&Bs[k][tc];
            *(float4*)&rb[4] = *(float4*)&Bs[k][tc + 4];
#pragma unroll
            for (int i = 0; i < 8; i++)
#pragma unroll
                for (int j = 0; j < 8; j++) acc[i][j] += ra[i] * rb[j];
        }
        __syncthreads();
    }

    int rowb = by * 128, colb = bx * 128;
    // zero the diagonal inside diagonal blocks
    if (bx == by) {
#pragma unroll
        for (int i = 0; i < 8; i++)
#pragma unroll
            for (int j = 0; j < 8; j++)
                if (tr + i == tc + j) acc[i][j] = 0.f;
    }
    // normal store
#pragma unroll
    for (int i = 0; i < 8; i++) {
        size_t base = (size_t)(rowb + tr + i) * NNODE + colb + tc;
#pragma unroll
        for (int j = 0; j < 8; j += 4) {
            float4 v = make_float4(acc[i][j], acc[i][j+1], acc[i][j+2], acc[i][j+3]);
            *(float4*)&C[base + j] = v;
        }
    }
    // mirrored store (skip diagonal block: fully covered above)
    if (bx != by) {
#pragma unroll
        for (int j = 0; j < 8; j++) {
            size_t base = (size_t)(colb + tc + j) * NNODE + rowb + tr;
#pragma unroll
            for (int i = 0; i < 8; i += 4) {
                float4 v = make_float4(acc[i][j], acc[i+1][j], acc[i+2][j], acc[i+3][j]);
                *(float4*)&C[base + i] = v;
            }
        }
    }
}

// ---------------- launch ----------------
extern "C" void kernel_launch(void* const* d_in, const int* in_sizes, int n_in,
                              void* d_out, int out_size) {
    const float* x   = (const float*)d_in[0];
    const int*   ei  = (const int*)d_in[1];
    const float* W1  = (const float*)d_in[2];
    const float* b1  = (const float*)d_in[3];
    const float* W2  = (const float*)d_in[4];
    const float* b2  = (const float*)d_in[5];
    const float* fcW = (const float*)d_in[6];
    const float* fcb = (const float*)d_in[7];

    const int* src = ei;
    const int* dst = ei + NEDGE;

    float* outp   = (float*)d_out;
    float* logits = outp;                          // [8192, 64]
    float* dis    = outp + (size_t)NNODE * NO;     // [8192, 8192]

    float *p1, *p2, *p3, *pxh, *pxn;
    cudaGetSymbolAddress((void**)&p1,  g_buf1);
    cudaGetSymbolAddress((void**)&p2,  g_buf2);
    cudaGetSymbolAddress((void**)&p3,  g_buf3);
    cudaGetSymbolAddress((void**)&pxh, g_xhid);
    cudaGetSymbolAddress((void**)&pxn, g_xn);

    // CSR build (recomputed every call: deterministic, graph-replay safe)
    k_zero<<<NNODE / 256, 256>>>();
    k_count<<<NEDGE / 256, 256>>>(dst);
    k_scan<<<1, 1024>>>();
    k_fill<<<NEDGE / 256, 256>>>(src, dst);

    dim3 gconv(NH / 128, NNODE / 128);   // (4, 64)
    // conv1
    k_sgemm_nn<<<gconv, 256>>>(x, W1, p1, KF, NH);
    k_agg<<<NNODE, 128>>>(p1, b1, p2, 1);
    // conv2
    k_sgemm_nn<<<gconv, 256>>>(p2, W2, p3, NH, NH);
    k_agg<<<NNODE, 128>>>(p3, b2, pxh, 1);   // x_hid = relu(conv2)
    // heads
    k_norm<<<NNODE, 128>>>(pxh, pxn);
    k_fc<<<NNODE / 32, 256>>>(pxh, fcW, fcb, logits);
    dim3 gdis(NNODE / 128, NNODE / 128); // (64, 64), lower-left half early-exits
    k_dis<<<gdis, 256>>>(pxn, dis);
}

// round 4
// speedup vs baseline: 2.4564x; 2.4564x over previous
#include <cuda_runtime.h>
#include <cuda_bf16.h>
#include <cstdint>
#include <math.h>

#define NNODE 8192
#define NEDGE 262144
#define KF    512
#define NH    512
#define NO    64

#define NCHUNK 24              // K=1536 bf16 in chunks of 64
#define STAGE_BYTES 32768      // A 16KB + B 16KB per stage
#define SMEM_TOTAL 67584       // max(2*STAGE_BYTES, 128*132*4 transpose buf)

// ---------------- scratch ----------------
__device__ float g_buf1[NNODE * NH];
__device__ float g_buf2[NNODE * NH];
__device__ float g_buf3[NNODE * NH];
__device__ float g_xhid[NNODE * NH];
__device__ float g_xn  [NNODE * NH];
__device__ float g_dinv[NNODE];
__device__ int   g_cnt [NNODE];
__device__ int   g_off [NNODE + 1];
__device__ int   g_cur [NNODE];
__device__ int   g_ssrc[NEDGE];
__device__ __nv_bfloat16 g_Ahi[NNODE * NH];
__device__ __nv_bfloat16 g_Alo[NNODE * NH];
__device__ __nv_bfloat16 g_Whi[NH * NH];
__device__ __nv_bfloat16 g_Wlo[NH * NH];

// ---------------- PTX helpers (all plain sm_80-era: valid on compute_103) ----------------
__device__ __forceinline__ uint32_t smem_u32(const void* p) {
    uint32_t a;
    asm("{ .reg .u64 t; cvta.to.shared.u64 t, %1; cvt.u32.u64 %0, t; }" : "=r"(a) : "l"(p));
    return a;
}
__device__ __forceinline__ void cp_async16(uint32_t saddr, const void* g) {
    asm volatile("cp.async.cg.shared.global [%0], [%1], 16;" :: "r"(saddr), "l"(g) : "memory");
}
__device__ __forceinline__ void cp_commit() {
    asm volatile("cp.async.commit_group;" ::: "memory");
}
template <int N> __device__ __forceinline__ void cp_wait() {
    asm volatile("cp.async.wait_group %0;" :: "n"(N) : "memory");
}
__device__ __forceinline__ void ldsm_x4(uint32_t& r0, uint32_t& r1, uint32_t& r2, uint32_t& r3,
                                        uint32_t a) {
    asm volatile("ldmatrix.sync.aligned.m8n8.x4.shared.b16 {%0,%1,%2,%3}, [%4];"
                 : "=r"(r0), "=r"(r1), "=r"(r2), "=r"(r3) : "r"(a));
}
__device__ __forceinline__ void ldsm_x2(uint32_t& r0, uint32_t& r1, uint32_t a) {
    asm volatile("ldmatrix.sync.aligned.m8n8.x2.shared.b16 {%0,%1}, [%2];"
                 : "=r"(r0), "=r"(r1) : "r"(a));
}
__device__ __forceinline__ void mma_bf16(float* d, const uint32_t* a, const uint32_t* b) {
    asm volatile(
        "mma.sync.aligned.m16n8k16.row.col.f32.bf16.bf16.f32 "
        "{%0,%1,%2,%3}, {%4,%5,%6,%7}, {%8,%9}, {%0,%1,%2,%3};"
        : "+f"(d[0]), "+f"(d[1]), "+f"(d[2]), "+f"(d[3])
        : "r"(a[0]), "r"(a[1]), "r"(a[2]), "r"(a[3]), "r"(b[0]), "r"(b[1]));
}

// ---------------- CSR build ----------------
__global__ void k_zero() {
    int i = blockIdx.x * blockDim.x + threadIdx.x;
    if (i < NNODE) g_cnt[i] = 0;
}
__global__ void k_count(const int* __restrict__ dst) {
    int i = blockIdx.x * blockDim.x + threadIdx.x;
    if (i < NEDGE) atomicAdd(&g_cnt[dst[i]], 1);
}
__global__ void k_scan() {
    __shared__ int ssum[1024];
    int t = threadIdx.x;
    int base = t * 8;
    int c[8];
    int s = 0;
#pragma unroll
    for (int i = 0; i < 8; i++) { c[i] = g_cnt[base + i]; s += c[i]; }
    ssum[t] = s;
    __syncthreads();
    for (int off = 1; off < 1024; off <<= 1) {
        int v = (t >= off) ? ssum[t - off] : 0;
        __syncthreads();
        ssum[t] += v;
        __syncthreads();
    }
    int excl = ssum[t] - s;
#pragma unroll
    for (int i = 0; i < 8; i++) {
        g_off[base + i] = excl;
        g_cur[base + i] = excl;
        g_dinv[base + i] = rsqrtf((float)c[i] + 1.0f);
        excl += c[i];
    }
    if (t == 1023) g_off[NNODE] = ssum[1023];
}
__global__ void k_fill(const int* __restrict__ src, const int* __restrict__ dst) {
    int i = blockIdx.x * blockDim.x + threadIdx.x;
    if (i < NEDGE) {
        int p = atomicAdd(&g_cur[dst[i]], 1);
        g_ssrc[p] = src[i];
    }
}

// ---------------- split fp32 -> bf16 hi/lo ----------------
__global__ void k_splitF(const float* __restrict__ X,
                         __nv_bfloat16* __restrict__ H, __nv_bfloat16* __restrict__ L) {
    int i = (blockIdx.x * blockDim.x + threadIdx.x) * 4;
    float4 v = *(const float4*)(X + i);
    __nv_bfloat16 h0 = __float2bfloat16(v.x), h1 = __float2bfloat16(v.y);
    __nv_bfloat16 h2 = __float2bfloat16(v.z), h3 = __float2bfloat16(v.w);
    __nv_bfloat162* H2 = (__nv_bfloat162*)(H + i);
    H2[0] = __nv_bfloat162(h0, h1);
    H2[1] = __nv_bfloat162(h2, h3);
    __nv_bfloat16 l0 = __float2bfloat16(v.x - __bfloat162float(h0));
    __nv_bfloat16 l1 = __float2bfloat16(v.y - __bfloat162float(h1));
    __nv_bfloat16 l2 = __float2bfloat16(v.z - __bfloat162float(h2));
    __nv_bfloat16 l3 = __float2bfloat16(v.w - __bfloat162float(h3));
    __nv_bfloat162* L2 = (__nv_bfloat162*)(L + i);
    L2[0] = __nv_bfloat162(l0, l1);
    L2[1] = __nv_bfloat162(l2, l3);
}

// ---------------- transpose + split W[512,512] ----------------
__global__ void k_prepW(const float* __restrict__ W,
                        __nv_bfloat16* __restrict__ TH, __nv_bfloat16* __restrict__ TL) {
    __shared__ float t[32][33];
    int tx = threadIdx.x, ty = threadIdx.y;
    int k0 = blockIdx.x * 32, n0 = blockIdx.y * 32;
    t[ty][tx] = W[(size_t)(k0 + ty) * NH + n0 + tx];
    __syncthreads();
    float v = t[tx][ty];
    __nv_bfloat16 h = __float2bfloat16(v);
    __nv_bfloat16 l = __float2bfloat16(v - __bfloat162float(h));
    TH[(size_t)(n0 + ty) * NH + k0 + tx] = h;
    TL[(size_t)(n0 + ty) * NH + k0 + tx] = l;
}

// ---------------- HMMA GEMM: C = A @ B^T, K=1536 compensated bf16 ----------------
// MODE 0: plain store (ldc cols). MODE 1: symmetric dis (upper tri + mirror, zero diag).
__device__ __forceinline__ void load_chunk(
    const __nv_bfloat16* __restrict__ Asrc, const __nv_bfloat16* __restrict__ Bsrc,
    int rowbA, int rowbB, int kbyte, uint32_t sA, int tid)
{
#pragma unroll
    for (int j = 0; j < 4; j++) {
        int u = tid + 256 * j;               // 0..1023
        int r = u >> 3, q = u & 7;
        int off = r * 128 + ((q * 16) ^ ((r & 7) * 16));
        cp_async16(sA + off,         (const char*)Asrc + (size_t)(rowbA + r) * 1024 + kbyte + q * 16);
        cp_async16(sA + 16384 + off, (const char*)Bsrc + (size_t)(rowbB + r) * 1024 + kbyte + q * 16);
    }
}

template <int MODE>
__global__ __launch_bounds__(256, 2) void k_mma_gemm(
    const __nv_bfloat16* __restrict__ Ahi, const __nv_bfloat16* __restrict__ Alo,
    const __nv_bfloat16* __restrict__ Bhi, const __nv_bfloat16* __restrict__ Blo,
    float* __restrict__ C, int ldc)
{
    int bx = blockIdx.x, by = blockIdx.y;
    if (MODE == 1 && bx < by) return;

    extern __shared__ char smem[];
    uint32_t sb = smem_u32(smem);
    int tid = threadIdx.x;
    int lane = tid & 31, wid = tid >> 5;
    int wm = wid & 1, wn = wid >> 1;         // warp tile: rows wm*64, cols wn*32

    int rowbA = by * 128;
    int rowbB = bx * 128;

    float acc[4][4][4];
#pragma unroll
    for (int mt = 0; mt < 4; mt++)
#pragma unroll
        for (int nt = 0; nt < 4; nt++)
#pragma unroll
            for (int e = 0; e < 4; e++) acc[mt][nt][e] = 0.f;

    // per-lane ldmatrix base offsets (within a stage's A or B region)
    // A: row = wm*64 + mt*16 + (lane&15); kbyte = kt*32 + (lane>>4)*16
    int arow = wm * 64 + (lane & 15);
    int akb  = (lane >> 4) * 16;
    // B: row = wn*32 + nt*8 + (lane&7); kbyte = kt*32 + ((lane>>3)&1)*16
    int brow = wn * 32 + (lane & 7);
    int bkb  = ((lane >> 3) & 1) * 16;

    // prologue
    {
        const __nv_bfloat16* As = Ahi;
        const __nv_bfloat16* Bs = Bhi;
        load_chunk(As, Bs, rowbA, rowbB, 0, sb, tid);
        cp_commit();
    }

    for (int c = 0; c < NCHUNK; c++) {
        if (c + 1 < NCHUNK) {
            int cn = c + 1;
            int part = cn >> 3;
            const __nv_bfloat16* As = (part == 1) ? Alo : Ahi;
            const __nv_bfloat16* Bs = (part == 2) ? Blo : Bhi;
            load_chunk(As, Bs, rowbA, rowbB, (cn & 7) * 128, sb + (cn & 1) * STAGE_BYTES, tid);
            cp_commit();
            cp_wait<1>();
        } else {
            cp_wait<0>();
        }
        __syncthreads();

        uint32_t stA = sb + (c & 1) * STAGE_BYTES;
        uint32_t stB = stA + 16384;
#pragma unroll
        for (int kt = 0; kt < 4; kt++) {
            uint32_t af[4][4], bf[4][2];
#pragma unroll
            for (int mt = 0; mt < 4; mt++) {
                int r = arow + mt * 16;
                int kb = kt * 32 + akb;
                uint32_t ad = stA + r * 128 + (kb ^ ((r & 7) * 16));
                ldsm_x4(af[mt][0], af[mt][1], af[mt][2], af[mt][3], ad);
            }
#pragma unroll
            for (int nt = 0; nt < 4; nt++) {
                int r = brow + nt * 8;
                int kb = kt * 32 + bkb;
                uint32_t bd = stB + r * 128 + (kb ^ ((r & 7) * 16));
                ldsm_x2(bf[nt][0], bf[nt][1], bd);
            }
#pragma unroll
            for (int mt = 0; mt < 4; mt++)
#pragma unroll
                for (int nt = 0; nt < 4; nt++)
                    mma_bf16(acc[mt][nt], af[mt], bf[nt]);
        }
        __syncthreads();
    }

    // ---------------- epilogue ----------------
    int lr0 = wm * 64 + (lane >> 2);         // local row (and +8)
    int lc0 = wn * 32 + (lane & 3) * 2;      // local col (and +1)
    float* T = (float*)smem;                 // [128][132] transpose buffer (MODE 1)

#pragma unroll
    for (int mt = 0; mt < 4; mt++) {
#pragma unroll
        for (int nt = 0; nt < 4; nt++) {
            float* a = acc[mt][nt];
            int lr = lr0 + mt * 16;
            int lc = lc0 + nt * 8;
            if (MODE == 1 && bx == by) {
                if (lr == lc) a[0] = 0.f;
                if (lr == lc + 1) a[1] = 0.f;
                if (lr + 8 == lc) a[2] = 0.f;
                if (lr + 8 == lc + 1) a[3] = 0.f;
            }
            size_t g0 = (size_t)(by * 128 + lr) * ldc + bx * 128 + lc;
            *(float2*)&C[g0] = make_float2(a[0], a[1]);
            *(float2*)&C[g0 + 8 * ldc] = make_float2(a[2], a[3]);
            if (MODE == 1 && bx != by) {
                T[lc * 132 + lr] = a[0];
                T[(lc + 1) * 132 + lr] = a[1];
                T[lc * 132 + lr + 8] = a[2];
                T[(lc + 1) * 132 + lr + 8] = a[3];
            }
        }
    }

    if (MODE == 1 && bx != by) {
        __syncthreads();
        int mrow = tid >> 1;                 // 0..127 (mirror row = original col)
        int half = (tid & 1) * 64;
        size_t mbase = (size_t)(bx * 128 + mrow) * ldc + by * 128 + half;
        const float* Tr = &T[mrow * 132 + half];
#pragma unroll
        for (int i = 0; i < 64; i += 4) {
            float4 v = make_float4(Tr[i], Tr[i + 1], Tr[i + 2], Tr[i + 3]);
            *(float4*)&C[mbase + i] = v;
        }
    }
}

// ---------------- GCN aggregation ----------------
__global__ __launch_bounds__(128) void k_agg(
    const float* __restrict__ h, const float* __restrict__ bias,
    float* __restrict__ out, int do_relu)
{
    int d = blockIdx.x;
    int t = threadIdx.x;
    const float4* h4 = (const float4*)h;
    float4 acc = make_float4(0.f, 0.f, 0.f, 0.f);
    int e = g_off[d], end = g_off[d + 1];
    for (; e < end; ++e) {
        int s = g_ssrc[e];
        float w = g_dinv[s];
        float4 v = h4[(size_t)s * 128 + t];
        acc.x += v.x * w; acc.y += v.y * w; acc.z += v.z * w; acc.w += v.w * w;
    }
    float wd = g_dinv[d];
    float w2 = wd * wd;
    float4 sv = h4[(size_t)d * 128 + t];
    float4 bb = ((const float4*)bias)[t];
    float4 r;
    r.x = acc.x * wd + sv.x * w2 + bb.x;
    r.y = acc.y * wd + sv.y * w2 + bb.y;
    r.z = acc.z * wd + sv.z * w2 + bb.z;
    r.w = acc.w * wd + sv.w * w2 + bb.w;
    if (do_relu) {
        r.x = fmaxf(r.x, 0.f); r.y = fmaxf(r.y, 0.f);
        r.z = fmaxf(r.z, 0.f); r.w = fmaxf(r.w, 0.f);
    }
    ((float4*)out)[(size_t)d * 128 + t] = r;
}

// ---------------- row L2-normalize ----------------
__global__ __launch_bounds__(128) void k_norm(const float* __restrict__ x, float* __restrict__ xn) {
    __shared__ float red[4];
    int r = blockIdx.x, t = threadIdx.x;
    float4 v = ((const float4*)x)[(size_t)r * 128 + t];
    float s = v.x * v.x + v.y * v.y + v.z * v.z + v.w * v.w;
#pragma unroll
    for (int o = 16; o; o >>= 1) s += __shfl_xor_sync(0xffffffffu, s, o);
    if ((t & 31) == 0) red[t >> 5] = s;
    __syncthreads();
    float tot = red[0] + red[1] + red[2] + red[3];
    float inv = (tot > 0.f) ? rsqrtf(tot) : 0.f;
    ((float4*)xn)[(size_t)r * 128 + t] = make_float4(v.x * inv, v.y * inv, v.z * inv, v.w * inv);
}

// ---------------- FC head ----------------
__global__ __launch_bounds__(256) void k_fc(
    const float* __restrict__ X, const float* __restrict__ W,
    const float* __restrict__ bias, float* __restrict__ out)
{
    __shared__ float Xs[32][68];
    __shared__ float Ws[64][NO];
    int tid = threadIdx.x;
    int tx = tid & 63;
    int tg = tid >> 6;
    int row0 = blockIdx.x * 32;
    float acc[8];
#pragma unroll
    for (int i = 0; i < 8; i++) acc[i] = 0.f;

    for (int k0 = 0; k0 < NH; k0 += 64) {
        int xr = tid >> 3, xk = (tid & 7) * 8;
        *(float4*)&Xs[xr][xk]     = *(const float4*)&X[(size_t)(row0 + xr) * NH + k0 + xk];
        *(float4*)&Xs[xr][xk + 4] = *(const float4*)&X[(size_t)(row0 + xr) * NH + k0 + xk + 4];
        int wr = tid >> 2, wc = (tid & 3) * 16;
#pragma unroll
        for (int q = 0; q < 16; q += 4)
            *(float4*)&Ws[wr][wc + q] = *(const float4*)&W[(size_t)(k0 + wr) * NO + wc + q];
        __syncthreads();
#pragma unroll 16
        for (int k = 0; k < 64; k++) {
            float w = Ws[k][tx];
#pragma unroll
            for (int i = 0; i < 8; i++) acc[i] += Xs[tg * 8 + i][k] * w;
        }
        __syncthreads();
    }
#pragma unroll
    for (int i = 0; i < 8; i++)
        out[(size_t)(row0 + tg * 8 + i) * NO + tx] = acc[i] + bias[tx];
}

// ---------------- launch ----------------
extern "C" void kernel_launch(void* const* d_in, const int* in_sizes, int n_in,
                              void* d_out, int out_size) {
    const float* x   = (const float*)d_in[0];
    const int*   ei  = (const int*)d_in[1];
    const float* W1  = (const float*)d_in[2];
    const float* b1  = (const float*)d_in[3];
    const float* W2  = (const float*)d_in[4];
    const float* b2  = (const float*)d_in[5];
    const float* fcW = (const float*)d_in[6];
    const float* fcb = (const float*)d_in[7];

    const int* src = ei;
    const int* dst = ei + NEDGE;

    float* outp   = (float*)d_out;
    float* logits = outp;
    float* dis    = outp + (size_t)NNODE * NO;

    float *p1, *p2, *p3, *pxh, *pxn;
    cudaGetSymbolAddress((void**)&p1,  g_buf1);
    cudaGetSymbolAddress((void**)&p2,  g_buf2);
    cudaGetSymbolAddress((void**)&p3,  g_buf3);
    cudaGetSymbolAddress((void**)&pxh, g_xhid);
    cudaGetSymbolAddress((void**)&pxn, g_xn);
    __nv_bfloat16 *ahi, *alo, *whi, *wlo;
    cudaGetSymbolAddress((void**)&ahi, g_Ahi);
    cudaGetSymbolAddress((void**)&alo, g_Alo);
    cudaGetSymbolAddress((void**)&whi, g_Whi);
    cudaGetSymbolAddress((void**)&wlo, g_Wlo);

    cudaFuncSetAttribute(k_mma_gemm<0>, cudaFuncAttributeMaxDynamicSharedMemorySize, SMEM_TOTAL);
    cudaFuncSetAttribute(k_mma_gemm<1>, cudaFuncAttributeMaxDynamicSharedMemorySize, SMEM_TOTAL);

    // CSR build
    k_zero<<<NNODE / 256, 256>>>();
    k_count<<<NEDGE / 256, 256>>>(dst);
    k_scan<<<1, 1024>>>();
    k_fill<<<NEDGE / 256, 256>>>(src, dst);

    dim3 tblk(32, 32);
    dim3 tgrd(16, 16);
    int splitGrid = NNODE * NH / (256 * 4);
    dim3 gconv(NH / 128, NNODE / 128);       // (4, 64)

    // conv1
    k_prepW<<<tgrd, tblk>>>(W1, whi, wlo);
    k_splitF<<<splitGrid, 256>>>(x, ahi, alo);
    k_mma_gemm<0><<<gconv, 256, SMEM_TOTAL>>>(ahi, alo, whi, wlo, p1, NH);
    k_agg<<<NNODE, 128>>>(p1, b1, p2, 1);
    // conv2
    k_prepW<<<tgrd, tblk>>>(W2, whi, wlo);
    k_splitF<<<splitGrid, 256>>>(p2, ahi, alo);
    k_mma_gemm<0><<<gconv, 256, SMEM_TOTAL>>>(ahi, alo, whi, wlo, p3, NH);
    k_agg<<<NNODE, 128>>>(p3, b2, pxh, 1);
    // heads
    k_norm<<<NNODE, 128>>>(pxh, pxn);
    k_fc<<<NNODE / 32, 256>>>(pxh, fcW, fcb, logits);
    k_splitF<<<splitGrid, 256>>>(pxn, ahi, alo);
    dim3 gdis(NNODE / 128, NNODE / 128);     // (64, 64)
    k_mma_gemm<1><<<gdis, 256, SMEM_TOTAL>>>(ahi, alo, ahi, alo, dis, NNODE);
}